// round 3
// baseline (speedup 1.0000x reference)
#include <cuda_runtime.h>
#include <math.h>

// ---------------------------------------------------------------------------
// Problem constants: B=1, S=2048, H=4096, NH=32, NKV=8, HD=128
// ---------------------------------------------------------------------------
#define S_LEN 2048
#define HDIM  4096
#define NH    32
#define NKV   8
#define HD    128
#define SCALING 0.08838834764831843f  // 128^-0.5

// Intermediate buffers (device globals: no runtime allocation allowed)
__device__ float g_q [S_LEN * NH  * HD];   // 2048 x 4096
__device__ float g_k [S_LEN * NKV * HD];   // 2048 x 1024
__device__ float g_v [S_LEN * NKV * HD];   // 2048 x 1024
__device__ float g_ao[S_LEN * NH  * HD];   // 2048 x 4096
// Fallback scratch for attention weights if the harness output does not
// include them (536 MB; unused if out_size covers both outputs).
__device__ float g_w_scratch[(size_t)NH * S_LEN * S_LEN];

#define BM 128
#define BN 128
#define BK 8
#define TM 8
#define TN 8

// ---------------------------------------------------------------------------
// C[z] = alpha * A[z] @ B[z>>bShift]^T
// A[M,K] lda ; B[N,K] ldb ; C[M,N] ldc. All tile dims must divide M,N,K.
// causal!=0: skip blocks with bx > by (BM==BN).
// ---------------------------------------------------------------------------
__global__ __launch_bounds__(256) void gemm_nt(
    const float* __restrict__ A, const float* __restrict__ B, float* __restrict__ C,
    int M, int N, int K, int lda, int ldb, int ldc,
    long long bsA, long long bsB, int bShift, long long bsC,
    float alpha, int causal)
{
    const int bx = blockIdx.x, by = blockIdx.y, bz = blockIdx.z;
    if (causal && bx > by) return;

    A += (long long)bz * bsA;
    B += (long long)(bz >> bShift) * bsB;
    C += (long long)bz * bsC;

    __shared__ __align__(16) float As[BK][BM];
    __shared__ __align__(16) float Bs[BK][BN];

    const int tid  = threadIdx.x;
    const int tx   = tid & 15;
    const int ty   = tid >> 4;
    const int lrow = tid >> 1;         // 0..127
    const int lcol = (tid & 1) * 4;    // 0 or 4

    const float* Ag = A + (long long)(by * BM + lrow) * lda + lcol;
    const float* Bg = B + (long long)(bx * BN + lrow) * ldb + lcol;

    float acc[TM][TN];
    #pragma unroll
    for (int i = 0; i < TM; i++)
        #pragma unroll
        for (int j = 0; j < TN; j++) acc[i][j] = 0.f;

    for (int k0 = 0; k0 < K; k0 += BK) {
        float4 a4 = *reinterpret_cast<const float4*>(Ag + k0);
        float4 b4 = *reinterpret_cast<const float4*>(Bg + k0);
        As[lcol + 0][lrow] = a4.x; As[lcol + 1][lrow] = a4.y;
        As[lcol + 2][lrow] = a4.z; As[lcol + 3][lrow] = a4.w;
        Bs[lcol + 0][lrow] = b4.x; Bs[lcol + 1][lrow] = b4.y;
        Bs[lcol + 2][lrow] = b4.z; Bs[lcol + 3][lrow] = b4.w;
        __syncthreads();

        #pragma unroll
        for (int kk = 0; kk < BK; kk++) {
            float ra[TM], rb[TN];
            float4 t0 = *reinterpret_cast<const float4*>(&As[kk][ty * TM]);
            float4 t1 = *reinterpret_cast<const float4*>(&As[kk][ty * TM + 4]);
            ra[0]=t0.x; ra[1]=t0.y; ra[2]=t0.z; ra[3]=t0.w;
            ra[4]=t1.x; ra[5]=t1.y; ra[6]=t1.z; ra[7]=t1.w;
            float4 u0 = *reinterpret_cast<const float4*>(&Bs[kk][tx * TN]);
            float4 u1 = *reinterpret_cast<const float4*>(&Bs[kk][tx * TN + 4]);
            rb[0]=u0.x; rb[1]=u0.y; rb[2]=u0.z; rb[3]=u0.w;
            rb[4]=u1.x; rb[5]=u1.y; rb[6]=u1.z; rb[7]=u1.w;
            #pragma unroll
            for (int i = 0; i < TM; i++)
                #pragma unroll
                for (int j = 0; j < TN; j++)
                    acc[i][j] = fmaf(ra[i], rb[j], acc[i][j]);
        }
        __syncthreads();
    }

    #pragma unroll
    for (int i = 0; i < TM; i++) {
        float* Crow = C + (long long)(by * BM + ty * TM + i) * ldc + bx * BN + tx * TN;
        float4 v0, v1;
        v0.x = acc[i][0]*alpha; v0.y = acc[i][1]*alpha;
        v0.z = acc[i][2]*alpha; v0.w = acc[i][3]*alpha;
        v1.x = acc[i][4]*alpha; v1.y = acc[i][5]*alpha;
        v1.z = acc[i][6]*alpha; v1.w = acc[i][7]*alpha;
        *reinterpret_cast<float4*>(Crow)     = v0;
        *reinterpret_cast<float4*>(Crow + 4) = v1;
    }
}

// ---------------------------------------------------------------------------
// C[z] = alpha * A[z] @ B[z>>bShift]   (B not transposed)
// A[M,K] lda ; B[K,N] ldb ; C[M,N] ldc.
// causal!=0: K loop clipped to (by+1)*BM (weights beyond are exactly zero).
// ---------------------------------------------------------------------------
__global__ __launch_bounds__(256) void gemm_nn(
    const float* __restrict__ A, const float* __restrict__ B, float* __restrict__ C,
    int M, int N, int K, int lda, int ldb, int ldc,
    long long bsA, long long bsB, int bShift, long long bsC,
    float alpha, int causal)
{
    const int bx = blockIdx.x, by = blockIdx.y, bz = blockIdx.z;

    A += (long long)bz * bsA;
    B += (long long)(bz >> bShift) * bsB;
    C += (long long)bz * bsC;

    __shared__ __align__(16) float As[BK][BM];
    __shared__ __align__(16) float Bs[BK][BN];

    const int tid  = threadIdx.x;
    const int tx   = tid & 15;
    const int ty   = tid >> 4;
    const int arow = tid >> 1;
    const int acol = (tid & 1) * 4;
    const int brow = tid >> 5;          // 0..7
    const int bcol = (tid & 31) * 4;    // 0..124

    const float* Ag = A + (long long)(by * BM + arow) * lda + acol;
    const float* Bg = B + (long long)brow * ldb + bx * BN + bcol;

    const int Keff = causal ? min(K, (by + 1) * BM) : K;

    float acc[TM][TN];
    #pragma unroll
    for (int i = 0; i < TM; i++)
        #pragma unroll
        for (int j = 0; j < TN; j++) acc[i][j] = 0.f;

    for (int k0 = 0; k0 < Keff; k0 += BK) {
        float4 a4 = *reinterpret_cast<const float4*>(Ag + k0);
        float4 b4 = *reinterpret_cast<const float4*>(Bg + (long long)k0 * ldb);
        As[acol + 0][arow] = a4.x; As[acol + 1][arow] = a4.y;
        As[acol + 2][arow] = a4.z; As[acol + 3][arow] = a4.w;
        *reinterpret_cast<float4*>(&Bs[brow][bcol]) = b4;
        __syncthreads();

        #pragma unroll
        for (int kk = 0; kk < BK; kk++) {
            float ra[TM], rb[TN];
            float4 t0 = *reinterpret_cast<const float4*>(&As[kk][ty * TM]);
            float4 t1 = *reinterpret_cast<const float4*>(&As[kk][ty * TM + 4]);
            ra[0]=t0.x; ra[1]=t0.y; ra[2]=t0.z; ra[3]=t0.w;
            ra[4]=t1.x; ra[5]=t1.y; ra[6]=t1.z; ra[7]=t1.w;
            float4 u0 = *reinterpret_cast<const float4*>(&Bs[kk][tx * TN]);
            float4 u1 = *reinterpret_cast<const float4*>(&Bs[kk][tx * TN + 4]);
            rb[0]=u0.x; rb[1]=u0.y; rb[2]=u0.z; rb[3]=u0.w;
            rb[4]=u1.x; rb[5]=u1.y; rb[6]=u1.z; rb[7]=u1.w;
            #pragma unroll
            for (int i = 0; i < TM; i++)
                #pragma unroll
                for (int j = 0; j < TN; j++)
                    acc[i][j] = fmaf(ra[i], rb[j], acc[i][j]);
        }
        __syncthreads();
    }

    #pragma unroll
    for (int i = 0; i < TM; i++) {
        float* Crow = C + (long long)(by * BM + ty * TM + i) * ldc + bx * BN + tx * TN;
        float4 v0, v1;
        v0.x = acc[i][0]*alpha; v0.y = acc[i][1]*alpha;
        v0.z = acc[i][2]*alpha; v0.w = acc[i][3]*alpha;
        v1.x = acc[i][4]*alpha; v1.y = acc[i][5]*alpha;
        v1.z = acc[i][6]*alpha; v1.w = acc[i][7]*alpha;
        *reinterpret_cast<float4*>(Crow)     = v0;
        *reinterpret_cast<float4*>(Crow + 4) = v1;
    }
}

// ---------------------------------------------------------------------------
// RoPE in place: x[s, h, d<64]  -> x1*cos[s,d]   - x2*sin[s,d]
//                x[s, h, d>=64] -> x2*cos[s,d+64] + x1*sin[s,d+64]
// ---------------------------------------------------------------------------
__global__ void rope_kernel(float* __restrict__ x,
                            const float* __restrict__ cosb,
                            const float* __restrict__ sinb, int nh)
{
    int i = blockIdx.x * blockDim.x + threadIdx.x;
    int total = S_LEN * nh * 64;
    if (i >= total) return;
    int d = i & 63;
    int h = (i >> 6) % nh;
    int s = i / (64 * nh);
    float c1 = cosb[s * HD + d];
    float s1 = sinb[s * HD + d];
    float c2 = cosb[s * HD + d + 64];
    float s2 = sinb[s * HD + d + 64];
    float* p = x + (long long)s * nh * HD + h * HD;
    float x1 = p[d];
    float x2 = p[d + 64];
    p[d]      = x1 * c1 - x2 * s1;
    p[d + 64] = x2 * c2 + x1 * s2;
}

// ---------------------------------------------------------------------------
// Causal softmax in place over weights W[NH, S, S]. One block per (q, h) row.
// Writes exact 0 for k > q (matches -1e9 mask underflow in reference).
// ---------------------------------------------------------------------------
__global__ __launch_bounds__(256) void softmax_causal(float* __restrict__ W)
{
    const int q = blockIdx.x;
    const int h = blockIdx.y;
    float* row = W + ((long long)h * S_LEN + q) * S_LEN;
    const int L = q + 1;
    const int tid = threadIdx.x;
    __shared__ float red[32];

    // --- max ---
    float mx = -3.402823e38f;
    for (int k = tid; k < L; k += 256) mx = fmaxf(mx, row[k]);
    #pragma unroll
    for (int o = 16; o; o >>= 1) mx = fmaxf(mx, __shfl_xor_sync(0xffffffffu, mx, o));
    if ((tid & 31) == 0) red[tid >> 5] = mx;
    __syncthreads();
    if (tid < 32) {
        float w = (tid < 8) ? red[tid] : -3.402823e38f;
        #pragma unroll
        for (int o = 4; o; o >>= 1) w = fmaxf(w, __shfl_xor_sync(0xffffffffu, w, o));
        if (tid == 0) red[0] = w;
    }
    __syncthreads();
    mx = red[0];
    __syncthreads();

    // --- sum exp ---
    float s = 0.f;
    for (int k = tid; k < L; k += 256) s += expf(row[k] - mx);
    #pragma unroll
    for (int o = 16; o; o >>= 1) s += __shfl_xor_sync(0xffffffffu, s, o);
    if ((tid & 31) == 0) red[tid >> 5] = s;
    __syncthreads();
    if (tid < 32) {
        float w = (tid < 8) ? red[tid] : 0.f;
        #pragma unroll
        for (int o = 4; o; o >>= 1) w += __shfl_xor_sync(0xffffffffu, w, o);
        if (tid == 0) red[0] = w;
    }
    __syncthreads();
    const float inv = 1.f / red[0];

    // --- normalize + zero upper triangle ---
    for (int k = tid; k < S_LEN; k += 256)
        row[k] = (k < L) ? expf(row[k] - mx) * inv : 0.f;
}

// ---------------------------------------------------------------------------
extern "C" void kernel_launch(void* const* d_in, const int* in_sizes, int n_in,
                              void* d_out, int out_size)
{
    const float* hs   = (const float*)d_in[0];  // [1,2048,4096]
    const float* wq   = (const float*)d_in[1];  // [4096,4096]
    const float* wk   = (const float*)d_in[2];  // [1024,4096]
    const float* wv   = (const float*)d_in[3];  // [1024,4096]
    const float* wo   = (const float*)d_in[4];  // [4096,4096]
    const float* cosb = (const float*)d_in[5];  // [1,2048,128]
    const float* sinb = (const float*)d_in[6];  // [1,2048,128]
    (void)in_sizes; (void)n_in;

    float* out = (float*)d_out;

    const long long OUT_ELEMS = (long long)S_LEN * NH * HD;              // 8,388,608
    const long long W_ELEMS   = (long long)NH * S_LEN * S_LEN;           // 134,217,728

    float *qp, *kp, *vp, *aop, *wsc;
    cudaGetSymbolAddress((void**)&qp,  g_q);
    cudaGetSymbolAddress((void**)&kp,  g_k);
    cudaGetSymbolAddress((void**)&vp,  g_v);
    cudaGetSymbolAddress((void**)&aop, g_ao);
    cudaGetSymbolAddress((void**)&wsc, g_w_scratch);

    // Output layout: concatenated (out, attn_weights). Fallback: scratch.
    float* W = ((long long)out_size >= OUT_ELEMS + W_ELEMS) ? (out + OUT_ELEMS) : wsc;

    // 1) QKV projections:  X @ Wx^T
    gemm_nt<<<dim3(NH * HD / BN,  S_LEN / BM), 256>>>(hs, wq, qp,
        S_LEN, NH * HD,  HDIM, HDIM, HDIM, NH * HD,  0, 0, 0, 0, 1.f, 0);
    gemm_nt<<<dim3(NKV * HD / BN, S_LEN / BM), 256>>>(hs, wk, kp,
        S_LEN, NKV * HD, HDIM, HDIM, HDIM, NKV * HD, 0, 0, 0, 0, 1.f, 0);
    gemm_nt<<<dim3(NKV * HD / BN, S_LEN / BM), 256>>>(hs, wv, vp,
        S_LEN, NKV * HD, HDIM, HDIM, HDIM, NKV * HD, 0, 0, 0, 0, 1.f, 0);

    // 2) RoPE on Q and K (in place)
    rope_kernel<<<(S_LEN * NH  * 64 + 255) / 256, 256>>>(qp, cosb, sinb, NH);
    rope_kernel<<<(S_LEN * NKV * 64 + 255) / 256, 256>>>(kp, cosb, sinb, NKV);

    // 3) Scores: per head  Q_h @ K_{h/4}^T * scaling  (causal block skip)
    gemm_nt<<<dim3(S_LEN / BN, S_LEN / BM, NH), 256>>>(qp, kp, W,
        S_LEN, S_LEN, HD, NH * HD, NKV * HD, S_LEN,
        /*bsA=*/HD, /*bsB=*/HD, /*bShift=*/2, /*bsC=*/(long long)S_LEN * S_LEN,
        SCALING, 1);

    // 4) Causal softmax (in place; zeros upper triangle)
    softmax_causal<<<dim3(S_LEN, NH), 256>>>(W);

    // 5) attn_out = W_h @ V_{h/4}   (causal K clipping)
    gemm_nn<<<dim3(HD / BN, S_LEN / BM, NH), 256>>>(W, vp, aop,
        S_LEN, HD, S_LEN, S_LEN, NKV * HD, NH * HD,
        /*bsA=*/(long long)S_LEN * S_LEN, /*bsB=*/HD, /*bShift=*/2, /*bsC=*/HD,
        1.f, 1);

    // 6) out = attn_out @ wo^T
    gemm_nt<<<dim3(NH * HD / BN, S_LEN / BM), 256>>>(aop, wo, out,
        S_LEN, NH * HD, HDIM, HDIM, HDIM, NH * HD, 0, 0, 0, 0, 1.f, 0);
}

// round 4
// speedup vs baseline: 2.7669x; 2.7669x over previous
#include <cuda_runtime.h>
#include <math.h>
#include <stdint.h>

// ---------------------------------------------------------------------------
// Problem constants: B=1, S=2048, H=4096, NH=32, NKV=8, HD=128
// ---------------------------------------------------------------------------
#define S_LEN 2048
#define HDIM  4096
#define NH    32
#define NKV   8
#define HD    128
#define SCALING 0.08838834764831843f  // 128^-0.5

// Intermediate buffers (device globals: no runtime allocation allowed)
__device__ float g_q [S_LEN * NH  * HD];
__device__ float g_k [S_LEN * NKV * HD];
__device__ float g_v [S_LEN * NKV * HD];
__device__ float g_ao[S_LEN * NH  * HD];
__device__ float g_w_scratch[(size_t)NH * S_LEN * S_LEN];

// ---------------------------------------------------------------------------
// TF32 helpers
// ---------------------------------------------------------------------------
__device__ __forceinline__ uint32_t f2tf32(float x) {
    uint32_t u;
    asm("cvt.rna.tf32.f32 %0, %1;" : "=r"(u) : "f"(x));
    return u;
}

__device__ __forceinline__ void mma_tf32(float* c, const uint32_t* a, const uint32_t* b) {
    asm volatile(
        "mma.sync.aligned.m16n8k8.row.col.f32.tf32.tf32.f32 "
        "{%0,%1,%2,%3}, {%4,%5,%6,%7}, {%8,%9}, {%0,%1,%2,%3};\n"
        : "+f"(c[0]), "+f"(c[1]), "+f"(c[2]), "+f"(c[3])
        : "r"(a[0]), "r"(a[1]), "r"(a[2]), "r"(a[3]), "r"(b[0]), "r"(b[1]));
}

// Tile config: CTA 128x128x16, 8 warps (2x4), warp tile 64x32.
#define BM 128
#define BN 128
#define BK 16
#define AKP 20    // padded K stride for [row][k] tiles (conflict-free)
#define BNP 136   // padded N stride for [k][n] tiles (conflict-free)

// ---------------------------------------------------------------------------
// C[z] = alpha * A[z] @ B[z>>bShift]^T   (TF32 tensor cores)
// A[M,K] lda ; B[N,K] ldb ; C[M,N] ldc.
// causal!=0: skip blocks with bx > by.
// ---------------------------------------------------------------------------
__global__ __launch_bounds__(256) void mm_nt(
    const float* __restrict__ A, const float* __restrict__ B, float* __restrict__ C,
    int K, int lda, int ldb, int ldc,
    long long bsA, long long bsB, int bShift, long long bsC,
    float alpha, int causal)
{
    const int bx = blockIdx.x, by = blockIdx.y, bz = blockIdx.z;
    if (causal && bx > by) return;

    A += (long long)bz * bsA;
    B += (long long)(bz >> bShift) * bsB;
    C += (long long)bz * bsC;

    __shared__ uint32_t As[2][BM * AKP];
    __shared__ uint32_t Bs[2][BN * AKP];

    const int tid  = threadIdx.x;
    const int lane = tid & 31;
    const int w    = tid >> 5;
    const int wm   = w >> 2;       // 0..1
    const int wn   = w & 3;        // 0..3
    const int t4   = lane >> 2;    // 0..7
    const int l4   = lane & 3;     // 0..3

    // Global load pattern: each thread loads 2 float4 per operand tile.
    const int grow = tid >> 2;        // 0..63
    const int gk4  = (tid & 3) * 4;   // 0,4,8,12
    const float* Ag = A + (long long)(by * BM + grow) * lda + gk4;
    const float* Bg = B + (long long)(bx * BN + grow) * ldb + gk4;
    const int s0 = grow * AKP + gk4;
    const int s1 = s0 + 64 * AKP;

    float acc[4][4][4];
    #pragma unroll
    for (int i = 0; i < 4; i++)
        #pragma unroll
        for (int j = 0; j < 4; j++)
            #pragma unroll
            for (int r = 0; r < 4; r++) acc[i][j][r] = 0.f;

    const int NT = K / BK;

    // Prologue: tile 0 -> buffer 0
    {
        float4 a0 = *reinterpret_cast<const float4*>(Ag);
        float4 a1 = *reinterpret_cast<const float4*>(Ag + 64 * (long long)lda);
        float4 b0 = *reinterpret_cast<const float4*>(Bg);
        float4 b1 = *reinterpret_cast<const float4*>(Bg + 64 * (long long)ldb);
        As[0][s0+0]=f2tf32(a0.x); As[0][s0+1]=f2tf32(a0.y); As[0][s0+2]=f2tf32(a0.z); As[0][s0+3]=f2tf32(a0.w);
        As[0][s1+0]=f2tf32(a1.x); As[0][s1+1]=f2tf32(a1.y); As[0][s1+2]=f2tf32(a1.z); As[0][s1+3]=f2tf32(a1.w);
        Bs[0][s0+0]=f2tf32(b0.x); Bs[0][s0+1]=f2tf32(b0.y); Bs[0][s0+2]=f2tf32(b0.z); Bs[0][s0+3]=f2tf32(b0.w);
        Bs[0][s1+0]=f2tf32(b1.x); Bs[0][s1+1]=f2tf32(b1.y); Bs[0][s1+2]=f2tf32(b1.z); Bs[0][s1+3]=f2tf32(b1.w);
    }
    __syncthreads();

    for (int t = 0; t < NT; t++) {
        float4 na0, na1, nb0, nb1;
        if (t + 1 < NT) {
            const float* Ap = Ag + (t + 1) * BK;
            const float* Bp = Bg + (t + 1) * BK;
            na0 = *reinterpret_cast<const float4*>(Ap);
            na1 = *reinterpret_cast<const float4*>(Ap + 64 * (long long)lda);
            nb0 = *reinterpret_cast<const float4*>(Bp);
            nb1 = *reinterpret_cast<const float4*>(Bp + 64 * (long long)ldb);
        }

        const uint32_t* as = As[t & 1];
        const uint32_t* bs = Bs[t & 1];
        #pragma unroll
        for (int ks = 0; ks < 2; ks++) {
            const int k0 = ks * 8;
            uint32_t af[4][4], bf[4][2];
            #pragma unroll
            for (int mi = 0; mi < 4; mi++) {
                const int r = wm * 64 + mi * 16 + t4;
                af[mi][0] = as[r * AKP + k0 + l4];
                af[mi][1] = as[(r + 8) * AKP + k0 + l4];
                af[mi][2] = as[r * AKP + k0 + 4 + l4];
                af[mi][3] = as[(r + 8) * AKP + k0 + 4 + l4];
            }
            #pragma unroll
            for (int ni = 0; ni < 4; ni++) {
                const int n = wn * 32 + ni * 8 + t4;
                bf[ni][0] = bs[n * AKP + k0 + l4];
                bf[ni][1] = bs[n * AKP + k0 + 4 + l4];
            }
            #pragma unroll
            for (int mi = 0; mi < 4; mi++)
                #pragma unroll
                for (int ni = 0; ni < 4; ni++)
                    mma_tf32(acc[mi][ni], af[mi], bf[ni]);
        }

        if (t + 1 < NT) {
            uint32_t* ad = As[(t + 1) & 1];
            uint32_t* bd = Bs[(t + 1) & 1];
            ad[s0+0]=f2tf32(na0.x); ad[s0+1]=f2tf32(na0.y); ad[s0+2]=f2tf32(na0.z); ad[s0+3]=f2tf32(na0.w);
            ad[s1+0]=f2tf32(na1.x); ad[s1+1]=f2tf32(na1.y); ad[s1+2]=f2tf32(na1.z); ad[s1+3]=f2tf32(na1.w);
            bd[s0+0]=f2tf32(nb0.x); bd[s0+1]=f2tf32(nb0.y); bd[s0+2]=f2tf32(nb0.z); bd[s0+3]=f2tf32(nb0.w);
            bd[s1+0]=f2tf32(nb1.x); bd[s1+1]=f2tf32(nb1.y); bd[s1+2]=f2tf32(nb1.z); bd[s1+3]=f2tf32(nb1.w);
            __syncthreads();
        }
    }

    // Epilogue
    #pragma unroll
    for (int mi = 0; mi < 4; mi++) {
        const int r0 = by * BM + wm * 64 + mi * 16 + t4;
        #pragma unroll
        for (int ni = 0; ni < 4; ni++) {
            const int c = bx * BN + wn * 32 + ni * 8 + 2 * l4;
            float2 v0 = make_float2(acc[mi][ni][0] * alpha, acc[mi][ni][1] * alpha);
            float2 v1 = make_float2(acc[mi][ni][2] * alpha, acc[mi][ni][3] * alpha);
            *reinterpret_cast<float2*>(&C[(long long)r0 * ldc + c])       = v0;
            *reinterpret_cast<float2*>(&C[(long long)(r0 + 8) * ldc + c]) = v1;
        }
    }
}

// ---------------------------------------------------------------------------
// C[z] = alpha * A[z] @ B[z>>bShift]   (TF32 tensor cores, B not transposed)
// A[M,K] lda ; B[K,N] ldb ; C[M,N] ldc.
// causal!=0: K clipped to (by+1)*BM (weights beyond are exactly zero).
// ---------------------------------------------------------------------------
__global__ __launch_bounds__(256) void mm_nn(
    const float* __restrict__ A, const float* __restrict__ B, float* __restrict__ C,
    int K, int lda, int ldb, int ldc,
    long long bsA, long long bsB, int bShift, long long bsC,
    float alpha, int causal)
{
    const int bx = blockIdx.x, by = blockIdx.y, bz = blockIdx.z;

    A += (long long)bz * bsA;
    B += (long long)(bz >> bShift) * bsB;
    C += (long long)bz * bsC;

    __shared__ uint32_t As[2][BM * AKP];
    __shared__ uint32_t Bs[2][BK * BNP];

    const int tid  = threadIdx.x;
    const int lane = tid & 31;
    const int w    = tid >> 5;
    const int wm   = w >> 2;
    const int wn   = w & 3;
    const int t4   = lane >> 2;
    const int l4   = lane & 3;

    // A tile load (same as nt)
    const int arow = tid >> 2;
    const int ak4  = (tid & 3) * 4;
    const float* Ag = A + (long long)(by * BM + arow) * lda + ak4;
    const int a0i = arow * AKP + ak4;
    const int a1i = a0i + 64 * AKP;

    // B tile load: rows = k (0..15), cols = n (0..127); 2 float4 / thread
    const int brow = tid >> 5;             // 0..7
    const int bc4  = (tid & 31) * 4;       // 0..124
    const float* Bg = B + (long long)brow * ldb + bx * BN + bc4;
    const int b0i = brow * BNP + bc4;
    const int b1i = b0i + 8 * BNP;

    const int Keff = causal ? min(K, (by + 1) * BM) : K;
    const int NT = Keff / BK;

    float acc[4][4][4];
    #pragma unroll
    for (int i = 0; i < 4; i++)
        #pragma unroll
        for (int j = 0; j < 4; j++)
            #pragma unroll
            for (int r = 0; r < 4; r++) acc[i][j][r] = 0.f;

    {
        float4 a0 = *reinterpret_cast<const float4*>(Ag);
        float4 a1 = *reinterpret_cast<const float4*>(Ag + 64 * (long long)lda);
        float4 b0 = *reinterpret_cast<const float4*>(Bg);
        float4 b1 = *reinterpret_cast<const float4*>(Bg + 8 * (long long)ldb);
        As[0][a0i+0]=f2tf32(a0.x); As[0][a0i+1]=f2tf32(a0.y); As[0][a0i+2]=f2tf32(a0.z); As[0][a0i+3]=f2tf32(a0.w);
        As[0][a1i+0]=f2tf32(a1.x); As[0][a1i+1]=f2tf32(a1.y); As[0][a1i+2]=f2tf32(a1.z); As[0][a1i+3]=f2tf32(a1.w);
        Bs[0][b0i+0]=f2tf32(b0.x); Bs[0][b0i+1]=f2tf32(b0.y); Bs[0][b0i+2]=f2tf32(b0.z); Bs[0][b0i+3]=f2tf32(b0.w);
        Bs[0][b1i+0]=f2tf32(b1.x); Bs[0][b1i+1]=f2tf32(b1.y); Bs[0][b1i+2]=f2tf32(b1.z); Bs[0][b1i+3]=f2tf32(b1.w);
    }
    __syncthreads();

    for (int t = 0; t < NT; t++) {
        float4 na0, na1, nb0, nb1;
        if (t + 1 < NT) {
            const float* Ap = Ag + (t + 1) * BK;
            const float* Bp = Bg + (long long)(t + 1) * BK * ldb;
            na0 = *reinterpret_cast<const float4*>(Ap);
            na1 = *reinterpret_cast<const float4*>(Ap + 64 * (long long)lda);
            nb0 = *reinterpret_cast<const float4*>(Bp);
            nb1 = *reinterpret_cast<const float4*>(Bp + 8 * (long long)ldb);
        }

        const uint32_t* as = As[t & 1];
        const uint32_t* bs = Bs[t & 1];
        #pragma unroll
        for (int ks = 0; ks < 2; ks++) {
            const int k0 = ks * 8;
            uint32_t af[4][4], bf[4][2];
            #pragma unroll
            for (int mi = 0; mi < 4; mi++) {
                const int r = wm * 64 + mi * 16 + t4;
                af[mi][0] = as[r * AKP + k0 + l4];
                af[mi][1] = as[(r + 8) * AKP + k0 + l4];
                af[mi][2] = as[r * AKP + k0 + 4 + l4];
                af[mi][3] = as[(r + 8) * AKP + k0 + 4 + l4];
            }
            #pragma unroll
            for (int ni = 0; ni < 4; ni++) {
                const int n = wn * 32 + ni * 8 + t4;
                bf[ni][0] = bs[(k0 + l4) * BNP + n];
                bf[ni][1] = bs[(k0 + 4 + l4) * BNP + n];
            }
            #pragma unroll
            for (int mi = 0; mi < 4; mi++)
                #pragma unroll
                for (int ni = 0; ni < 4; ni++)
                    mma_tf32(acc[mi][ni], af[mi], bf[ni]);
        }

        if (t + 1 < NT) {
            uint32_t* ad = As[(t + 1) & 1];
            uint32_t* bd = Bs[(t + 1) & 1];
            ad[a0i+0]=f2tf32(na0.x); ad[a0i+1]=f2tf32(na0.y); ad[a0i+2]=f2tf32(na0.z); ad[a0i+3]=f2tf32(na0.w);
            ad[a1i+0]=f2tf32(na1.x); ad[a1i+1]=f2tf32(na1.y); ad[a1i+2]=f2tf32(na1.z); ad[a1i+3]=f2tf32(na1.w);
            bd[b0i+0]=f2tf32(nb0.x); bd[b0i+1]=f2tf32(nb0.y); bd[b0i+2]=f2tf32(nb0.z); bd[b0i+3]=f2tf32(nb0.w);
            bd[b1i+0]=f2tf32(nb1.x); bd[b1i+1]=f2tf32(nb1.y); bd[b1i+2]=f2tf32(nb1.z); bd[b1i+3]=f2tf32(nb1.w);
            __syncthreads();
        }
    }

    #pragma unroll
    for (int mi = 0; mi < 4; mi++) {
        const int r0 = by * BM + wm * 64 + mi * 16 + t4;
        #pragma unroll
        for (int ni = 0; ni < 4; ni++) {
            const int c = bx * BN + wn * 32 + ni * 8 + 2 * l4;
            float2 v0 = make_float2(acc[mi][ni][0] * alpha, acc[mi][ni][1] * alpha);
            float2 v1 = make_float2(acc[mi][ni][2] * alpha, acc[mi][ni][3] * alpha);
            *reinterpret_cast<float2*>(&C[(long long)r0 * ldc + c])       = v0;
            *reinterpret_cast<float2*>(&C[(long long)(r0 + 8) * ldc + c]) = v1;
        }
    }
}

// ---------------------------------------------------------------------------
// RoPE in place
// ---------------------------------------------------------------------------
__global__ void rope_kernel(float* __restrict__ x,
                            const float* __restrict__ cosb,
                            const float* __restrict__ sinb, int nh)
{
    int i = blockIdx.x * blockDim.x + threadIdx.x;
    int total = S_LEN * nh * 64;
    if (i >= total) return;
    int d = i & 63;
    int h = (i >> 6) % nh;
    int s = i / (64 * nh);
    float c1 = cosb[s * HD + d];
    float s1 = sinb[s * HD + d];
    float c2 = cosb[s * HD + d + 64];
    float s2 = sinb[s * HD + d + 64];
    float* p = x + (long long)s * nh * HD + h * HD;
    float x1 = p[d];
    float x2 = p[d + 64];
    p[d]      = x1 * c1 - x2 * s1;
    p[d + 64] = x2 * c2 + x1 * s2;
}

// ---------------------------------------------------------------------------
// Causal softmax in place over W[NH, S, S]. Register-cached exp values:
// one read pass + one write pass, single expf evaluation per element.
// ---------------------------------------------------------------------------
__global__ __launch_bounds__(256) void softmax_causal(float* __restrict__ W)
{
    const int q = blockIdx.x;
    const int h = blockIdx.y;
    float* row = W + ((long long)h * S_LEN + q) * S_LEN;
    const int L = q + 1;
    const int tid = threadIdx.x;
    __shared__ float red[32];

    float vals[8];
    int cnt = 0;

    // --- load + max ---
    float mx = -3.402823e38f;
    for (int k = tid; k < L; k += 256) {
        float x = row[k];
        vals[cnt++] = x;
        mx = fmaxf(mx, x);
    }
    #pragma unroll
    for (int o = 16; o; o >>= 1) mx = fmaxf(mx, __shfl_xor_sync(0xffffffffu, mx, o));
    if ((tid & 31) == 0) red[tid >> 5] = mx;
    __syncthreads();
    if (tid < 32) {
        float w2 = (tid < 8) ? red[tid] : -3.402823e38f;
        #pragma unroll
        for (int o = 4; o; o >>= 1) w2 = fmaxf(w2, __shfl_xor_sync(0xffffffffu, w2, o));
        if (tid == 0) red[0] = w2;
    }
    __syncthreads();
    mx = red[0];
    __syncthreads();

    // --- exp + sum (values stay in registers) ---
    float s = 0.f;
    for (int i = 0; i < cnt; i++) {
        float e = expf(vals[i] - mx);
        vals[i] = e;
        s += e;
    }
    #pragma unroll
    for (int o = 16; o; o >>= 1) s += __shfl_xor_sync(0xffffffffu, s, o);
    if ((tid & 31) == 0) red[tid >> 5] = s;
    __syncthreads();
    if (tid < 32) {
        float w2 = (tid < 8) ? red[tid] : 0.f;
        #pragma unroll
        for (int o = 4; o; o >>= 1) w2 += __shfl_xor_sync(0xffffffffu, w2, o);
        if (tid == 0) red[0] = w2;
    }
    __syncthreads();
    const float inv = 1.f / red[0];

    // --- write normalized + zero upper triangle ---
    int i = 0;
    for (int k = tid; k < S_LEN; k += 256) {
        row[k] = (k < L) ? vals[i++] * inv : 0.f;
    }
}

// ---------------------------------------------------------------------------
extern "C" void kernel_launch(void* const* d_in, const int* in_sizes, int n_in,
                              void* d_out, int out_size)
{
    const float* hs   = (const float*)d_in[0];
    const float* wq   = (const float*)d_in[1];
    const float* wk   = (const float*)d_in[2];
    const float* wv   = (const float*)d_in[3];
    const float* wo   = (const float*)d_in[4];
    const float* cosb = (const float*)d_in[5];
    const float* sinb = (const float*)d_in[6];
    (void)in_sizes; (void)n_in;

    float* out = (float*)d_out;

    const long long OUT_ELEMS = (long long)S_LEN * NH * HD;
    const long long W_ELEMS   = (long long)NH * S_LEN * S_LEN;

    float *qp, *kp, *vp, *aop, *wsc;
    cudaGetSymbolAddress((void**)&qp,  g_q);
    cudaGetSymbolAddress((void**)&kp,  g_k);
    cudaGetSymbolAddress((void**)&vp,  g_v);
    cudaGetSymbolAddress((void**)&aop, g_ao);
    cudaGetSymbolAddress((void**)&wsc, g_w_scratch);

    float* W = ((long long)out_size >= OUT_ELEMS + W_ELEMS) ? (out + OUT_ELEMS) : wsc;

    // 1) QKV projections: X @ Wx^T
    mm_nt<<<dim3(NH * HD / BN,  S_LEN / BM), 256>>>(hs, wq, qp,
        HDIM, HDIM, HDIM, NH * HD,  0, 0, 0, 0, 1.f, 0);
    mm_nt<<<dim3(NKV * HD / BN, S_LEN / BM), 256>>>(hs, wk, kp,
        HDIM, HDIM, HDIM, NKV * HD, 0, 0, 0, 0, 1.f, 0);
    mm_nt<<<dim3(NKV * HD / BN, S_LEN / BM), 256>>>(hs, wv, vp,
        HDIM, HDIM, HDIM, NKV * HD, 0, 0, 0, 0, 1.f, 0);

    // 2) RoPE on Q and K (in place)
    rope_kernel<<<(S_LEN * NH  * 64 + 255) / 256, 256>>>(qp, cosb, sinb, NH);
    rope_kernel<<<(S_LEN * NKV * 64 + 255) / 256, 256>>>(kp, cosb, sinb, NKV);

    // 3) Scores: per head  Q_h @ K_{h/4}^T * scaling  (causal block skip)
    mm_nt<<<dim3(S_LEN / BN, S_LEN / BM, NH), 256>>>(qp, kp, W,
        HD, NH * HD, NKV * HD, S_LEN,
        /*bsA=*/HD, /*bsB=*/HD, /*bShift=*/2, /*bsC=*/(long long)S_LEN * S_LEN,
        SCALING, 1);

    // 4) Causal softmax (in place; zeros upper triangle)
    softmax_causal<<<dim3(S_LEN, NH), 256>>>(W);

    // 5) attn_out = W_h @ V_{h/4}   (causal K clipping)
    mm_nn<<<dim3(HD / BN, S_LEN / BM, NH), 256>>>(W, vp, aop,
        S_LEN, S_LEN, NKV * HD, NH * HD,
        /*bsA=*/(long long)S_LEN * S_LEN, /*bsB=*/HD, /*bShift=*/2, /*bsC=*/HD,
        1.f, 1);

    // 6) out = attn_out @ wo^T
    mm_nt<<<dim3(NH * HD / BN, S_LEN / BM), 256>>>(aop, wo, out,
        HDIM, HDIM, HDIM, NH * HD, 0, 0, 0, 0, 1.f, 0);
}